// round 2
// baseline (speedup 1.0000x reference)
#include <cuda_runtime.h>
#include <cuda_bf16.h>
#include <cfloat>
#include <math.h>

// ---------------- problem constants ----------------
#define BB 8
#define NN 2048
#define KK 20
#define PP 64      // patches
#define PS 32
#define DD 1024
#define TOK (BB * (PP + 1))   // 520 tokens
#define INNER 512
#define MLPD 2048
#define EC_PTS 32             // points per stats block

// ---------------- scratch (static device globals; no allocs allowed) ----------------
__device__ float g_h[BB * NN * 512];            // concat features [b][n][512]
__device__ float g_G[BB * NN * NN];             // gram matrix per batch (134 MB)
__device__ float g_sq[BB * NN];
__device__ int   g_knn[BB * NN * KK];
__device__ float g_wT[256 * 256];               // transposed edgeconv weight
__device__ float g_psum[512 * 1024];            // deterministic BN partials
__device__ float g_psq[512 * 1024];
__device__ float g_mean[1024];
__device__ float g_rstd[1024];
__device__ float g_y5[BB * NN * DD];            // conv5 output (67 MB)
__device__ float g_t[TOK * DD];
__device__ float g_ln[TOK * DD];
__device__ float g_qkv[TOK * 3 * INNER];
__device__ float g_z[TOK * INNER];
__device__ float g_ff[TOK * MLPD];

// ---------------- generic fp32 GEMM: C = act(A @ B + bias) (+C) ----------------
template <bool TRANSB, int ACT, bool ADDC>
__global__ void gemm_kernel(const float* __restrict__ A, int lda, size_t strideA,
                            const float* __restrict__ Bm, int ldb, size_t strideB,
                            const float* __restrict__ bias,
                            float* __restrict__ C, int ldc, size_t strideC,
                            int M, int N, int K)
{
    __shared__ float As[16][64];
    __shared__ float Bs[16][64];
    A  += (size_t)blockIdx.z * strideA;
    Bm += (size_t)blockIdx.z * strideB;
    C  += (size_t)blockIdx.z * strideC;
    int bm = blockIdx.y * 64, bn = blockIdx.x * 64;
    int tid = threadIdx.x;
    int ty = tid >> 4, tx = tid & 15;
    int aRow = tid >> 2;          // 0..63
    int aCol = (tid & 3) * 4;     // 0,4,8,12
    int bRow = tid >> 4;          // 0..15
    int bCol = (tid & 15) * 4;    // 0..60

    float acc[4][4];
#pragma unroll
    for (int i = 0; i < 4; i++)
#pragma unroll
        for (int j = 0; j < 4; j++) acc[i][j] = 0.f;

    for (int k0 = 0; k0 < K; k0 += 16) {
        int m = bm + aRow;
#pragma unroll
        for (int i = 0; i < 4; i++) {
            int k = k0 + aCol + i;
            As[aCol + i][aRow] = (m < M && k < K) ? A[(size_t)m * lda + k] : 0.f;
        }
        int kB = k0 + bRow;
#pragma unroll
        for (int i = 0; i < 4; i++) {
            int n = bn + bCol + i;
            float v = 0.f;
            if (n < N && kB < K)
                v = TRANSB ? Bm[(size_t)n * ldb + kB] : Bm[(size_t)kB * ldb + n];
            Bs[bRow][bCol + i] = v;
        }
        __syncthreads();
#pragma unroll
        for (int kk = 0; kk < 16; kk++) {
            float av[4], bv[4];
#pragma unroll
            for (int i = 0; i < 4; i++) av[i] = As[kk][ty * 4 + i];
#pragma unroll
            for (int j = 0; j < 4; j++) bv[j] = Bs[kk][tx * 4 + j];
#pragma unroll
            for (int i = 0; i < 4; i++)
#pragma unroll
                for (int j = 0; j < 4; j++) acc[i][j] += av[i] * bv[j];
        }
        __syncthreads();
    }
#pragma unroll
    for (int i = 0; i < 4; i++) {
        int m = bm + ty * 4 + i;
        if (m >= M) continue;
#pragma unroll
        for (int j = 0; j < 4; j++) {
            int n = bn + tx * 4 + j;
            if (n >= N) continue;
            float v = acc[i][j];
            if (bias) v += bias[n];
            if (ACT == 1) v = 0.5f * v * (1.f + erff(v * 0.70710678118654752f));
            size_t off = (size_t)m * ldc + n;
            if (ADDC) v += C[off];
            C[off] = v;
        }
    }
}

// ---------------- small helpers ----------------
__global__ void transpose_kernel(const float* __restrict__ w, float* __restrict__ wT,
                                 int O, int C2)
{
    int i = blockIdx.x * blockDim.x + threadIdx.x;
    if (i < O * C2) {
        int o = i / C2, c = i - o * C2;
        wT[c * O + o] = w[i];
    }
}

__global__ void diag_kernel(const float* __restrict__ G, float* __restrict__ sq)
{
    int bn = blockIdx.x * blockDim.x + threadIdx.x;
    if (bn < BB * NN) {
        int b = bn >> 11, n = bn & 2047;
        sq[bn] = G[((size_t)b * NN + n) * NN + n];
    }
}

// deterministic BN finalize: sequential sum over npart partials per channel
__global__ void bn_reduce(const float* __restrict__ psum, const float* __restrict__ psq,
                          int npart, int O, float cnt_inv,
                          float* __restrict__ mean, float* __restrict__ rstd)
{
    int o = blockIdx.x * blockDim.x + threadIdx.x;
    if (o >= O) return;
    float s = 0.f, s2 = 0.f;
    for (int i = 0; i < npart; i++) {
        s  += psum[(size_t)i * O + o];
        s2 += psq[(size_t)i * O + o];
    }
    float mu = s * cnt_inv;
    float var = s2 * cnt_inv - mu * mu;
    mean[o] = mu;
    rstd[o] = rsqrtf(var + 1e-5f);
}

// ---------------- kNN top-20 selection (iterative argmax, lowest-index ties) ----------------
__global__ void knn_select(const float* __restrict__ G, const float* __restrict__ sq,
                           int* __restrict__ out)
{
    int bn = blockIdx.x;
    int b = bn >> 11, n = bn & 2047;
    __shared__ float dist[NN];
    __shared__ float rv[128];
    __shared__ int ri[128];
    int tid = threadIdx.x;   // 128
    const float* row = G + ((size_t)b * NN + n) * NN;
    const float* sqb = sq + (b << 11);
    float sqn = sqb[n];
    for (int j = tid; j < NN; j += 128)
        dist[j] = 2.f * row[j] - sqn - sqb[j];
    __syncthreads();
    for (int sel = 0; sel < KK; sel++) {
        float bv = -FLT_MAX; int bi = 0x7fffffff;
        for (int j = tid; j < NN; j += 128) {
            float v = dist[j];
            if (v > bv) { bv = v; bi = j; }   // ascending j -> lowest idx kept on tie
        }
        rv[tid] = bv; ri[tid] = bi;
        __syncthreads();
        for (int s = 64; s > 0; s >>= 1) {
            if (tid < s) {
                float ov = rv[tid + s]; int oi = ri[tid + s];
                if (ov > rv[tid] || (ov == rv[tid] && oi < ri[tid])) { rv[tid] = ov; ri[tid] = oi; }
            }
            __syncthreads();
        }
        if (tid == 0) { out[bn * KK + sel] = ri[0]; dist[ri[0]] = -FLT_MAX; }
        __syncthreads();
    }
}

// ---------------- EdgeConv stats pass: block = EC_PTS points, thread = channel ----------------
__global__ void ec_stats(const float* __restrict__ feat, int stride, int C,
                         const int* __restrict__ knn,
                         const float* __restrict__ wT, int O,
                         float* __restrict__ psum, float* __restrict__ psq)
{
    int blk = blockIdx.x;
    int tid = threadIdx.x;       // == o
    extern __shared__ float sh[];
    float* ctr = sh;             // [C]
    float* f = sh + C;           // [KK][2C]
    __shared__ int sidx[KK];
    int C2 = 2 * C;
    float S = 0.f, S2 = 0.f;
    for (int pt = 0; pt < EC_PTS; pt++) {
        int bn = blk * EC_PTS + pt;
        int b = bn >> 11;
        const float* frow = feat + (size_t)bn * stride;
        for (int c = tid; c < C; c += blockDim.x) ctr[c] = frow[c];
        if (tid < KK) sidx[tid] = knn[bn * KK + tid];
        __syncthreads();
        for (int e = tid; e < KK * C; e += blockDim.x) {
            int kk = e / C, c = e - kk * C;
            int j = sidx[kk];
            float nb = feat[((size_t)(b << 11) + j) * stride + c];
            float cv = ctr[c];
            f[kk * C2 + c] = nb - cv;
            f[kk * C2 + C + c] = cv;
        }
        __syncthreads();
        float y[KK];
#pragma unroll
        for (int kk = 0; kk < KK; kk++) y[kk] = 0.f;
        for (int c = 0; c < C2; c++) {
            float wv = wT[c * O + tid];
            const float* fc = f + c;
#pragma unroll
            for (int kk = 0; kk < KK; kk++) y[kk] += wv * fc[kk * C2];
        }
#pragma unroll
        for (int kk = 0; kk < KK; kk++) { S += y[kk]; S2 += y[kk] * y[kk]; }
        __syncthreads();   // before next iter overwrites shared
    }
    psum[(size_t)blk * O + tid] = S;
    psq[(size_t)blk * O + tid] = S2;
}

// ---------------- EdgeConv apply pass: block = one point, thread = channel ----------------
__global__ void ec_apply(const float* __restrict__ feat, int stride, int C,
                         const int* __restrict__ knn,
                         const float* __restrict__ wT, int O,
                         const float* __restrict__ mean, const float* __restrict__ rstd,
                         const float* __restrict__ gam, const float* __restrict__ bet,
                         float* __restrict__ outH, int outOff)
{
    int bn = blockIdx.x;
    int b = bn >> 11;
    int tid = threadIdx.x;       // == o
    extern __shared__ float sh[];
    float* ctr = sh;             // [C]
    float* f = sh + C;           // [KK][2C]
    __shared__ int sidx[KK];
    const float* frow = feat + (size_t)bn * stride;
    for (int c = tid; c < C; c += blockDim.x) ctr[c] = frow[c];
    if (tid < KK) sidx[tid] = knn[bn * KK + tid];
    __syncthreads();
    int C2 = 2 * C;
    for (int e = tid; e < KK * C; e += blockDim.x) {
        int kk = e / C, c = e - kk * C;
        int j = sidx[kk];
        float nb = feat[((size_t)(b << 11) + j) * stride + c];
        float cv = ctr[c];
        f[kk * C2 + c] = nb - cv;
        f[kk * C2 + C + c] = cv;
    }
    __syncthreads();

    float y[KK];
#pragma unroll
    for (int kk = 0; kk < KK; kk++) y[kk] = 0.f;
    for (int c = 0; c < C2; c++) {
        float wv = wT[c * O + tid];
        const float* fc = f + c;
#pragma unroll
        for (int kk = 0; kk < KK; kk++) y[kk] += wv * fc[kk * C2];
    }
    float mu = mean[tid], rs = rstd[tid], gg = gam[tid], bb = bet[tid];
    float m = -FLT_MAX;
#pragma unroll
    for (int kk = 0; kk < KK; kk++) {
        float v = (y[kk] - mu) * rs * gg + bb;
        v = (v >= 0.f) ? v : 0.2f * v;
        m = fmaxf(m, v);
    }
    outH[(size_t)bn * 512 + outOff + tid] = m;
}

// ---------------- conv5 BN stats partials (deterministic, 64 blocks) ----------------
__global__ void bn5_partial(const float* __restrict__ y5, float* __restrict__ psum,
                            float* __restrict__ psq)
{
    int blk = blockIdx.x;         // 64 blocks
    int t0 = blk * 256;
    int tid = threadIdx.x;        // 256
    float s[4] = {0, 0, 0, 0}, s2[4] = {0, 0, 0, 0};
    for (int t = t0; t < t0 + 256; t++) {
        const float* row = y5 + (size_t)t * DD;
#pragma unroll
        for (int i = 0; i < 4; i++) {
            float v = row[tid + i * 256];
            s[i] += v; s2[i] += v * v;
        }
    }
#pragma unroll
    for (int i = 0; i < 4; i++) {
        psum[(size_t)blk * DD + tid + i * 256] = s[i];
        psq[(size_t)blk * DD + tid + i * 256] = s2[i];
    }
}

// ---------------- BN5 + leaky + patch max-pool + cls prepend ----------------
__global__ void pool_kernel(const float* __restrict__ y5, const float* __restrict__ mean,
                            const float* __restrict__ rstd, const float* __restrict__ g5,
                            const float* __restrict__ b5, const float* __restrict__ cls,
                            float* __restrict__ t)
{
    int tok = blockIdx.x;           // b*65 + l
    int b = tok / 65, l = tok - b * 65;
    int tid = threadIdx.x;          // 256
    if (l == 0) {
        for (int d = tid; d < DD; d += 256) t[(size_t)tok * DD + d] = cls[d];
    } else {
        int p = l - 1;
        int base = b * NN + p * PS;
        for (int d = tid; d < DD; d += 256) {
            float mu = mean[d], rs = rstd[d], gg = g5[d], bb = b5[d];
            float m = -FLT_MAX;
            for (int s = 0; s < PS; s++) {
                float v = y5[(size_t)(base + s) * DD + d];
                v = (v - mu) * rs * gg + bb;
                v = (v >= 0.f) ? v : 0.2f * v;
                m = fmaxf(m, v);
            }
            t[(size_t)tok * DD + d] = m;
        }
    }
}

// ---------------- LayerNorm (optionally fused with pos-embed residual add into t) ----------------
__global__ void ln_kernel(float* __restrict__ t, const float* __restrict__ pos,
                          const float* __restrict__ g, const float* __restrict__ b,
                          float* __restrict__ out)
{
    int tok = blockIdx.x, tid = threadIdx.x;    // 256 threads
    __shared__ float rs1[256], rs2[256];
    float* trow = t + (size_t)tok * DD;
    float loc[4];
    float s = 0.f, s2 = 0.f;
#pragma unroll
    for (int i = 0; i < 4; i++) {
        int d = tid + i * 256;
        float v = trow[d];
        if (pos) { v += pos[(size_t)tok * DD + d]; trow[d] = v; }
        loc[i] = v; s += v; s2 += v * v;
    }
    rs1[tid] = s; rs2[tid] = s2;
    __syncthreads();
    for (int st = 128; st > 0; st >>= 1) {
        if (tid < st) { rs1[tid] += rs1[tid + st]; rs2[tid] += rs2[tid + st]; }
        __syncthreads();
    }
    float mean = rs1[0] * (1.f / DD);
    float var = rs2[0] * (1.f / DD) - mean * mean;
    float rstd = rsqrtf(var + 1e-5f);
#pragma unroll
    for (int i = 0; i < 4; i++) {
        int d = tid + i * 256;
        out[(size_t)tok * DD + d] = (loc[i] - mean) * rstd * g[d] + b[d];
    }
}

// ---------------- attention: one block per (l, h, b) ----------------
__global__ void attn_kernel(const float* __restrict__ qkv, float* __restrict__ z)
{
    int l = blockIdx.x, hh = blockIdx.y, b = blockIdx.z;
    int tid = threadIdx.x;   // 128
    __shared__ float sq_[64];
    __shared__ float sc[65];
    __shared__ float sinv;
    const float* qrow = qkv + (size_t)(b * 65 + l) * 1536 + hh * 64;
    if (tid < 64) sq_[tid] = qrow[tid];
    __syncthreads();
    if (tid < 65) {
        const float* krow = qkv + (size_t)(b * 65 + tid) * 1536 + 512 + hh * 64;
        float s = 0.f;
#pragma unroll 16
        for (int d = 0; d < 64; d++) s += sq_[d] * krow[d];
        sc[tid] = s * 0.125f;
    }
    __syncthreads();
    if (tid == 0) {
        float mx = -FLT_MAX;
        for (int m = 0; m < 65; m++) mx = fmaxf(mx, sc[m]);
        float sum = 0.f;
        for (int m = 0; m < 65; m++) { float e = expf(sc[m] - mx); sc[m] = e; sum += e; }
        sinv = 1.f / sum;
    }
    __syncthreads();
    if (tid < 64) {
        float inv = sinv;
        float acc = 0.f;
        for (int m = 0; m < 65; m++) {
            const float* vrow = qkv + (size_t)(b * 65 + m) * 1536 + 1024 + hh * 64;
            acc += sc[m] * vrow[tid];
        }
        z[(size_t)(b * 65 + l) * INNER + hh * 64 + tid] = acc * inv;
    }
}

// ---------------- final output copy: out[b,p,d] = t[b*65+1+p, d] ----------------
__global__ void out_copy(const float* __restrict__ t, float* __restrict__ out)
{
    int i = blockIdx.x * blockDim.x + threadIdx.x;
    if (i < BB * PP * DD) {
        int d = i & (DD - 1);
        int bp = i >> 10;
        int b = bp >> 6, p = bp & 63;
        out[i] = t[((size_t)(b * 65 + 1 + p) << 10) + d];
    }
}

// ---------------- host driver ----------------
static void edge_layer(const float* featPtr, int lda, int C,
                       const float* w, const float* g, const float* b,
                       int O, int outOff,
                       float* h, float* G, float* sq, int* knn, float* wT,
                       float* psum, float* psq, float* mean, float* rstd)
{
    int C2 = 2 * C;
    transpose_kernel<<<(O * C2 + 255) / 256, 256>>>(w, wT, O, C2);
    dim3 gg(32, 32, BB);
    gemm_kernel<true, 0, false><<<gg, 256>>>(featPtr, lda, (size_t)NN * lda,
                                             featPtr, lda, (size_t)NN * lda,
                                             nullptr, G, NN, (size_t)NN * NN,
                                             NN, NN, C);
    diag_kernel<<<(BB * NN + 255) / 256, 256>>>(G, sq);
    knn_select<<<BB * NN, 128>>>(G, sq, knn);
    size_t sh = (size_t)(C + KK * C2) * sizeof(float);
    int nblk = BB * NN / EC_PTS;   // 512
    ec_stats<<<nblk, O, sh>>>(featPtr, lda, C, knn, wT, O, psum, psq);
    bn_reduce<<<(O + 255) / 256, 256>>>(psum, psq, nblk, O,
                                        1.f / (8.f * 2048.f * 20.f), mean, rstd);
    ec_apply<<<BB * NN, O, sh>>>(featPtr, lda, C, knn, wT, O,
                                 mean, rstd, g, b, h, outOff);
}

extern "C" void kernel_launch(void* const* d_in, const int* in_sizes, int n_in,
                              void* d_out, int out_size)
{
    const float* x      = (const float*)d_in[0];
    const float* pos    = (const float*)d_in[1];
    const float* w1 = (const float*)d_in[2];  const float* g1 = (const float*)d_in[3];  const float* b1 = (const float*)d_in[4];
    const float* w2 = (const float*)d_in[5];  const float* g2 = (const float*)d_in[6];  const float* b2 = (const float*)d_in[7];
    const float* w3 = (const float*)d_in[8];  const float* g3 = (const float*)d_in[9];  const float* b3 = (const float*)d_in[10];
    const float* w4 = (const float*)d_in[11]; const float* g4 = (const float*)d_in[12]; const float* b4 = (const float*)d_in[13];
    const float* w5 = (const float*)d_in[14]; const float* g5 = (const float*)d_in[15]; const float* b5 = (const float*)d_in[16];
    const float* cls    = (const float*)d_in[17];
    const float* ln1g   = (const float*)d_in[18];
    const float* ln1b   = (const float*)d_in[19];
    const float* wqkv   = (const float*)d_in[20];
    const float* wout   = (const float*)d_in[21];
    const float* bout   = (const float*)d_in[22];
    const float* ln2g   = (const float*)d_in[23];
    const float* ln2b   = (const float*)d_in[24];
    const float* wff1   = (const float*)d_in[25];
    const float* bff1   = (const float*)d_in[26];
    const float* wff2   = (const float*)d_in[27];
    const float* bff2   = (const float*)d_in[28];
    float* out = (float*)d_out;

    float *h, *G, *sq, *wT, *psum, *psq, *mean, *rstd, *y5, *t, *ln, *qkv, *z, *ff;
    int* knn;
    cudaGetSymbolAddress((void**)&h, g_h);
    cudaGetSymbolAddress((void**)&G, g_G);
    cudaGetSymbolAddress((void**)&sq, g_sq);
    cudaGetSymbolAddress((void**)&knn, g_knn);
    cudaGetSymbolAddress((void**)&wT, g_wT);
    cudaGetSymbolAddress((void**)&psum, g_psum);
    cudaGetSymbolAddress((void**)&psq, g_psq);
    cudaGetSymbolAddress((void**)&mean, g_mean);
    cudaGetSymbolAddress((void**)&rstd, g_rstd);
    cudaGetSymbolAddress((void**)&y5, g_y5);
    cudaGetSymbolAddress((void**)&t, g_t);
    cudaGetSymbolAddress((void**)&ln, g_ln);
    cudaGetSymbolAddress((void**)&qkv, g_qkv);
    cudaGetSymbolAddress((void**)&z, g_z);
    cudaGetSymbolAddress((void**)&ff, g_ff);

    // ---- DGCNN backbone ----
    edge_layer(x,       3,   3,   w1, g1, b1, 64,  0,   h, G, sq, knn, wT, psum, psq, mean, rstd);
    edge_layer(h + 0,   512, 64,  w2, g2, b2, 64,  64,  h, G, sq, knn, wT, psum, psq, mean, rstd);
    edge_layer(h + 64,  512, 64,  w3, g3, b3, 128, 128, h, G, sq, knn, wT, psum, psq, mean, rstd);
    edge_layer(h + 128, 512, 128, w4, g4, b4, 256, 256, h, G, sq, knn, wT, psum, psq, mean, rstd);

    // ---- conv5: y5[t, o] = h[t, :] . w5[o, :]  (M=16384, N=1024, K=512, TRANSB) ----
    {
        dim3 gg((DD + 63) / 64, (BB * NN + 63) / 64, 1);
        gemm_kernel<true, 0, false><<<gg, 256>>>(h, 512, 0, w5, 512, 0, nullptr,
                                                 y5, DD, 0, BB * NN, DD, 512);
        bn5_partial<<<BB * NN / 256, 256>>>(y5, psum, psq);
        bn_reduce<<<(DD + 255) / 256, 256>>>(psum, psq, BB * NN / 256, DD,
                                             1.f / (8.f * 2048.f), mean, rstd);
        pool_kernel<<<TOK, 256>>>(y5, mean, rstd, g5, b5, cls, t);
    }

    // ---- transformer ----
    for (int i = 0; i < 6; i++) {
        const float* wqkv_i = wqkv + (size_t)i * DD * 3 * INNER;
        const float* wout_i = wout + (size_t)i * INNER * DD;
        const float* bout_i = bout + (size_t)i * DD;
        const float* wff1_i = wff1 + (size_t)i * DD * MLPD;
        const float* bff1_i = bff1 + (size_t)i * MLPD;
        const float* wff2_i = wff2 + (size_t)i * MLPD * DD;
        const float* bff2_i = bff2 + (size_t)i * DD;

        ln_kernel<<<TOK, 256>>>(t, pos, ln1g + i * DD, ln1b + i * DD, ln);

        dim3 gq((3 * INNER + 63) / 64, (TOK + 63) / 64, 1);
        gemm_kernel<false, 0, false><<<gq, 256>>>(ln, DD, 0, wqkv_i, 3 * INNER, 0, nullptr,
                                                  qkv, 3 * INNER, 0, TOK, 3 * INNER, DD);

        attn_kernel<<<dim3(65, 8, BB), 128>>>(qkv, z);

        dim3 gp((DD + 63) / 64, (TOK + 63) / 64, 1);
        gemm_kernel<false, 0, true><<<gp, 256>>>(z, INNER, 0, wout_i, DD, 0, bout_i,
                                                 t, DD, 0, TOK, DD, INNER);

        ln_kernel<<<TOK, 256>>>(t, nullptr, ln2g + i * DD, ln2b + i * DD, ln);

        dim3 gf1((MLPD + 63) / 64, (TOK + 63) / 64, 1);
        gemm_kernel<false, 1, false><<<gf1, 256>>>(ln, DD, 0, wff1_i, MLPD, 0, bff1_i,
                                                   ff, MLPD, 0, TOK, MLPD, DD);

        dim3 gf2((DD + 63) / 64, (TOK + 63) / 64, 1);
        gemm_kernel<false, 0, true><<<gf2, 256>>>(ff, MLPD, 0, wff2_i, DD, 0, bff2_i,
                                                  t, DD, 0, TOK, DD, MLPD);
    }

    out_copy<<<(BB * PP * DD + 255) / 256, 256>>>(t, out);
}

// round 3
// speedup vs baseline: 1.5581x; 1.5581x over previous
#include <cuda_runtime.h>
#include <cuda_bf16.h>
#include <cfloat>
#include <math.h>

// ---------------- problem constants ----------------
#define BB 8
#define NN 2048
#define KK 20
#define PP 64
#define PS 32
#define DD 1024
#define TOK (BB * (PP + 1))   // 520
#define INNER 512
#define MLPD 2048
#define EROWS (BB * NN * KK)  // 327680 edge rows
#define SBLK 512              // stats partial blocks

// ---------------- scratch ----------------
__device__ float g_h[BB * NN * 512];
__device__ float g_G[BB * NN * NN];          // 134 MB
__device__ float g_sq[BB * NN];
__device__ int   g_knn[EROWS];
__device__ float g_ey[(size_t)EROWS * 256];  // 335 MB edge-MLP output
__device__ float g_psum[SBLK * 1024];
__device__ float g_psq[SBLK * 1024];
__device__ float g_mean[1024];
__device__ float g_rstd[1024];
__device__ float g_y5[BB * NN * DD];
__device__ float g_t[TOK * DD];
__device__ float g_ln[TOK * DD];
__device__ float g_qkv[TOK * 3 * INNER];
__device__ float g_z[TOK * INNER];
__device__ float g_ff[TOK * MLPD];

// ---------------- templated register-tiled SGEMM ----------------
// C = act(A@B + bias) (+C).  A:[M,K] lda. B:[K,N] ldb, or [N,K] if TRANSB.
template <int BM, int BN, int BK, int TM, int TN, bool TRANSB, int ACT, bool ADDC>
__global__ void sgemm(const float* __restrict__ A, int lda, size_t strideA,
                      const float* __restrict__ Bm, int ldb, size_t strideB,
                      const float* __restrict__ bias,
                      float* __restrict__ C, int ldc, size_t strideC,
                      int M, int N, int K)
{
    constexpr int THREADS = (BM / TM) * (BN / TN);
    constexpr int LA = BM * BK / THREADS;
    constexpr int LB = BK * BN / THREADS;
    __shared__ float As[BK][BM];
    __shared__ float Bs[BK][BN];
    A  += (size_t)blockIdx.z * strideA;
    Bm += (size_t)blockIdx.z * strideB;
    C  += (size_t)blockIdx.z * strideC;
    int bm = blockIdx.y * BM, bn = blockIdx.x * BN;
    int tid = threadIdx.x;
    int trow = tid / (BN / TN);
    int tcol = tid % (BN / TN);
    float acc[TM][TN];
#pragma unroll
    for (int i = 0; i < TM; i++)
#pragma unroll
        for (int j = 0; j < TN; j++) acc[i][j] = 0.f;

    for (int k0 = 0; k0 < K; k0 += BK) {
#pragma unroll
        for (int i = 0; i < LA; i++) {
            int e = i * THREADS + tid;
            int m = e / BK, k = e % BK;
            int gm = bm + m, gk = k0 + k;
            As[k][m] = (gm < M && gk < K) ? A[(size_t)gm * lda + gk] : 0.f;
        }
#pragma unroll
        for (int i = 0; i < LB; i++) {
            int e = i * THREADS + tid;
            int k, n;
            if (TRANSB) { n = e / BK; k = e % BK; }
            else        { k = e / BN; n = e % BN; }
            int gn = bn + n, gk = k0 + k;
            float v = 0.f;
            if (gn < N && gk < K)
                v = TRANSB ? Bm[(size_t)gn * ldb + gk] : Bm[(size_t)gk * ldb + gn];
            Bs[k][n] = v;
        }
        __syncthreads();
#pragma unroll
        for (int k = 0; k < BK; k++) {
            float a[TM], b[TN];
#pragma unroll
            for (int i = 0; i < TM; i++) a[i] = As[k][trow * TM + i];
#pragma unroll
            for (int j = 0; j < TN; j++) b[j] = Bs[k][tcol * TN + j];
#pragma unroll
            for (int i = 0; i < TM; i++)
#pragma unroll
                for (int j = 0; j < TN; j++) acc[i][j] += a[i] * b[j];
        }
        __syncthreads();
    }
#pragma unroll
    for (int i = 0; i < TM; i++) {
        int gm = bm + trow * TM + i;
        if (gm >= M) continue;
#pragma unroll
        for (int j = 0; j < TN; j++) {
            int gn = bn + tcol * TN + j;
            if (gn >= N) continue;
            float v = acc[i][j];
            if (bias) v += bias[gn];
            if (ACT == 1) v = 0.5f * v * (1.f + erff(v * 0.70710678118654752f));
            size_t off = (size_t)gm * ldc + gn;
            if (ADDC) v += C[off];
            C[off] = v;
        }
    }
}

// ---------------- gather-fused EdgeConv GEMM: y[r][o] = f(r,:) . w[o,:] ----------------
// row r = point*KK + kk ; f(r,c) = c<C ? feat[nbr][c]-feat[ctr][c] : feat[ctr][c-C]
__global__ void ec_gemm(const float* __restrict__ feat, int stride, int C,
                        const int* __restrict__ knn,
                        const float* __restrict__ w, int O,
                        float* __restrict__ y)
{
    const int BM = 128, BN = 128, BK = 8;
    __shared__ float As[BK][BM];
    __shared__ float Bs[BK][BN];
    __shared__ int s_nbr[BM], s_ctr[BM];
    int tid = threadIdx.x;                 // 256
    int bm = blockIdx.y * BM, bn0 = blockIdx.x * BN;
    int C2 = 2 * C;
    for (int i = tid; i < BM; i += 256) {
        int r = bm + i;
        int p = r / KK;
        int b = p >> 11;
        int j = knn[r];
        s_nbr[i] = ((b << 11) + j) * stride;
        s_ctr[i] = p * stride;
    }
    __syncthreads();

    int trow = tid >> 4, tcol = tid & 15;
    float acc[8][8];
#pragma unroll
    for (int i = 0; i < 8; i++)
#pragma unroll
        for (int j = 0; j < 8; j++) acc[i][j] = 0.f;

    for (int k0 = 0; k0 < C2; k0 += BK) {
#pragma unroll
        for (int i = 0; i < 4; i++) {
            int e = i * 256 + tid;
            int m = e >> 3, k = e & 7;
            int c = k0 + k;
            float v = 0.f;
            if (c < C2) {
                if (c < C) v = feat[s_nbr[m] + c] - feat[s_ctr[m] + c];
                else       v = feat[s_ctr[m] + c - C];
            }
            As[k][m] = v;
        }
#pragma unroll
        for (int i = 0; i < 4; i++) {
            int e = i * 256 + tid;
            int n = e >> 3, k = e & 7;
            int c = k0 + k;
            int col = bn0 + n;
            Bs[k][n] = (col < O && c < C2) ? w[col * C2 + c] : 0.f;
        }
        __syncthreads();
#pragma unroll
        for (int k = 0; k < 8; k++) {
            float a[8], b[8];
#pragma unroll
            for (int i = 0; i < 8; i++) a[i] = As[k][trow * 8 + i];
#pragma unroll
            for (int j = 0; j < 8; j++) b[j] = Bs[k][tcol * 8 + j];
#pragma unroll
            for (int i = 0; i < 8; i++)
#pragma unroll
                for (int j = 0; j < 8; j++) acc[i][j] += a[i] * b[j];
        }
        __syncthreads();
    }
#pragma unroll
    for (int i = 0; i < 8; i++) {
        int m = bm + trow * 8 + i;
#pragma unroll
        for (int j = 0; j < 8; j++) {
            int col = bn0 + tcol * 8 + j;
            if (col < O) y[(size_t)m * O + col] = acc[i][j];
        }
    }
}

// ---------------- deterministic BN stats over y rows ----------------
__global__ void ec_stats_y(const float* __restrict__ y, int O, int rowsPer,
                           float* __restrict__ psum, float* __restrict__ psq)
{
    int blk = blockIdx.x;        // SBLK
    int o = threadIdx.x;         // O threads
    float s = 0.f, s2 = 0.f;
    int r0 = blk * rowsPer;
    for (int r = r0; r < r0 + rowsPer; r++) {
        float v = y[(size_t)r * O + o];
        s += v; s2 += v * v;
    }
    psum[(size_t)blk * O + o] = s;
    psq[(size_t)blk * O + o] = s2;
}

__global__ void bn_reduce(const float* __restrict__ psum, const float* __restrict__ psq,
                          int npart, int O, float cnt_inv,
                          float* __restrict__ mean, float* __restrict__ rstd)
{
    int o = blockIdx.x * blockDim.x + threadIdx.x;
    if (o >= O) return;
    float s = 0.f, s2 = 0.f;
    for (int i = 0; i < npart; i++) {
        s  += psum[(size_t)i * O + o];
        s2 += psq[(size_t)i * O + o];
    }
    float mu = s * cnt_inv;
    float var = s2 * cnt_inv - mu * mu;
    mean[o] = mu;
    rstd[o] = rsqrtf(var + 1e-5f);
}

// ---------------- BN + lrelu + max over k, write to h column block ----------------
__global__ void ec_apply_y(const float* __restrict__ y, int O,
                           const float* __restrict__ mean, const float* __restrict__ rstd,
                           const float* __restrict__ gam, const float* __restrict__ bet,
                           float* __restrict__ outH, int outOff)
{
    int bn = blockIdx.x;
    int o = threadIdx.x;
    float mu = mean[o], rs = rstd[o], gg = gam[o], bb = bet[o];
    float m = -FLT_MAX;
    for (int kk = 0; kk < KK; kk++) {
        float v = y[((size_t)bn * KK + kk) * O + o];
        v = (v - mu) * rs * gg + bb;
        v = (v >= 0.f) ? v : 0.2f * v;
        m = fmaxf(m, v);
    }
    outH[(size_t)bn * 512 + outOff + o] = m;
}

// ---------------- helpers ----------------
__global__ void diag_kernel(const float* __restrict__ G, float* __restrict__ sq)
{
    int bn = blockIdx.x * blockDim.x + threadIdx.x;
    if (bn < BB * NN) {
        int b = bn >> 11, n = bn & 2047;
        sq[bn] = G[((size_t)b * NN + n) * NN + n];
    }
}

// ---------------- kNN top-20 (warp-shuffle reduce, 2 barriers/selection) ----------------
__global__ void knn_select(const float* __restrict__ G, const float* __restrict__ sq,
                           int* __restrict__ out)
{
    int bn = blockIdx.x;
    int b = bn >> 11, n = bn & 2047;
    __shared__ float dist[NN];
    __shared__ float wv[4];
    __shared__ int wi[4];
    int tid = threadIdx.x;   // 128
    int lane = tid & 31, warp = tid >> 5;
    const float* row = G + ((size_t)b * NN + n) * NN;
    const float* sqb = sq + (b << 11);
    float sqn = sqb[n];
    for (int j = tid; j < NN; j += 128)
        dist[j] = 2.f * row[j] - sqn - sqb[j];
    __syncthreads();
    for (int sel = 0; sel < KK; sel++) {
        float bv = -FLT_MAX; int bi = 0x7fffffff;
        for (int j = tid; j < NN; j += 128) {
            float v = dist[j];
            if (v > bv) { bv = v; bi = j; }
        }
#pragma unroll
        for (int off = 16; off > 0; off >>= 1) {
            float ov = __shfl_down_sync(0xffffffffu, bv, off);
            int oi = __shfl_down_sync(0xffffffffu, bi, off);
            if (ov > bv || (ov == bv && oi < bi)) { bv = ov; bi = oi; }
        }
        if (lane == 0) { wv[warp] = bv; wi[warp] = bi; }
        __syncthreads();
        if (tid == 0) {
            float fv = wv[0]; int fi = wi[0];
#pragma unroll
            for (int w = 1; w < 4; w++) {
                if (wv[w] > fv || (wv[w] == fv && wi[w] < fi)) { fv = wv[w]; fi = wi[w]; }
            }
            out[bn * KK + sel] = fi;
            dist[fi] = -FLT_MAX;
        }
        __syncthreads();
    }
}

// ---------------- conv5 BN partials ----------------
__global__ void bn5_partial(const float* __restrict__ y5, float* __restrict__ psum,
                            float* __restrict__ psq)
{
    int blk = blockIdx.x;         // 64
    int t0 = blk * 256;
    int tid = threadIdx.x;        // 256
    float s[4] = {0, 0, 0, 0}, s2[4] = {0, 0, 0, 0};
    for (int t = t0; t < t0 + 256; t++) {
        const float* row = y5 + (size_t)t * DD;
#pragma unroll
        for (int i = 0; i < 4; i++) {
            float v = row[tid + i * 256];
            s[i] += v; s2[i] += v * v;
        }
    }
#pragma unroll
    for (int i = 0; i < 4; i++) {
        psum[(size_t)blk * DD + tid + i * 256] = s[i];
        psq[(size_t)blk * DD + tid + i * 256] = s2[i];
    }
}

// ---------------- BN5 + leaky + patch max-pool + cls prepend ----------------
__global__ void pool_kernel(const float* __restrict__ y5, const float* __restrict__ mean,
                            const float* __restrict__ rstd, const float* __restrict__ g5,
                            const float* __restrict__ b5, const float* __restrict__ cls,
                            float* __restrict__ t)
{
    int tok = blockIdx.x;
    int b = tok / 65, l = tok - b * 65;
    int tid = threadIdx.x;          // 256
    if (l == 0) {
        for (int d = tid; d < DD; d += 256) t[(size_t)tok * DD + d] = cls[d];
    } else {
        int p = l - 1;
        int base = b * NN + p * PS;
        for (int d = tid; d < DD; d += 256) {
            float mu = mean[d], rs = rstd[d], gg = g5[d], bb = b5[d];
            float m = -FLT_MAX;
            for (int s = 0; s < PS; s++) {
                float v = y5[(size_t)(base + s) * DD + d];
                v = (v - mu) * rs * gg + bb;
                v = (v >= 0.f) ? v : 0.2f * v;
                m = fmaxf(m, v);
            }
            t[(size_t)tok * DD + d] = m;
        }
    }
}

// ---------------- LayerNorm (optional fused pos-add) ----------------
__global__ void ln_kernel(float* __restrict__ t, const float* __restrict__ pos,
                          const float* __restrict__ g, const float* __restrict__ b,
                          float* __restrict__ out)
{
    int tok = blockIdx.x, tid = threadIdx.x;    // 256
    __shared__ float rs1[256], rs2[256];
    float* trow = t + (size_t)tok * DD;
    float loc[4];
    float s = 0.f, s2 = 0.f;
#pragma unroll
    for (int i = 0; i < 4; i++) {
        int d = tid + i * 256;
        float v = trow[d];
        if (pos) { v += pos[(size_t)tok * DD + d]; trow[d] = v; }
        loc[i] = v; s += v; s2 += v * v;
    }
    rs1[tid] = s; rs2[tid] = s2;
    __syncthreads();
    for (int st = 128; st > 0; st >>= 1) {
        if (tid < st) { rs1[tid] += rs1[tid + st]; rs2[tid] += rs2[tid + st]; }
        __syncthreads();
    }
    float mean = rs1[0] * (1.f / DD);
    float var = rs2[0] * (1.f / DD) - mean * mean;
    float rstd = rsqrtf(var + 1e-5f);
#pragma unroll
    for (int i = 0; i < 4; i++) {
        int d = tid + i * 256;
        out[(size_t)tok * DD + d] = (loc[i] - mean) * rstd * g[d] + b[d];
    }
}

// ---------------- attention ----------------
__global__ void attn_kernel(const float* __restrict__ qkv, float* __restrict__ z)
{
    int l = blockIdx.x, hh = blockIdx.y, b = blockIdx.z;
    int tid = threadIdx.x;   // 128
    __shared__ float sq_[64];
    __shared__ float sc[65];
    __shared__ float sinv;
    const float* qrow = qkv + (size_t)(b * 65 + l) * 1536 + hh * 64;
    if (tid < 64) sq_[tid] = qrow[tid];
    __syncthreads();
    if (tid < 65) {
        const float* krow = qkv + (size_t)(b * 65 + tid) * 1536 + 512 + hh * 64;
        float s = 0.f;
#pragma unroll 16
        for (int d = 0; d < 64; d++) s += sq_[d] * krow[d];
        sc[tid] = s * 0.125f;
    }
    __syncthreads();
    if (tid == 0) {
        float mx = -FLT_MAX;
        for (int m = 0; m < 65; m++) mx = fmaxf(mx, sc[m]);
        float sum = 0.f;
        for (int m = 0; m < 65; m++) { float e = expf(sc[m] - mx); sc[m] = e; sum += e; }
        sinv = 1.f / sum;
    }
    __syncthreads();
    if (tid < 64) {
        float inv = sinv;
        float acc = 0.f;
        for (int m = 0; m < 65; m++) {
            const float* vrow = qkv + (size_t)(b * 65 + m) * 1536 + 1024 + hh * 64;
            acc += sc[m] * vrow[tid];
        }
        z[(size_t)(b * 65 + l) * INNER + hh * 64 + tid] = acc * inv;
    }
}

__global__ void out_copy(const float* __restrict__ t, float* __restrict__ out)
{
    int i = blockIdx.x * blockDim.x + threadIdx.x;
    if (i < BB * PP * DD) {
        int d = i & (DD - 1);
        int bp = i >> 10;
        int b = bp >> 6, p = bp & 63;
        out[i] = t[((size_t)(b * 65 + 1 + p) << 10) + d];
    }
}

// ---------------- host driver ----------------
static void edge_layer(const float* featPtr, int lda, int C,
                       const float* w, const float* g, const float* b,
                       int O, int outOff,
                       float* h, float* G, float* sq, int* knn, float* ey,
                       float* psum, float* psq, float* mean, float* rstd)
{
    // gram
    dim3 gg(NN / 128, NN / 128, BB);
    sgemm<128, 128, 8, 8, 8, true, 0, false><<<gg, 256>>>(
        featPtr, lda, (size_t)NN * lda, featPtr, lda, (size_t)NN * lda,
        nullptr, G, NN, (size_t)NN * NN, NN, NN, C);
    diag_kernel<<<(BB * NN + 255) / 256, 256>>>(G, sq);
    knn_select<<<BB * NN, 128>>>(G, sq, knn);
    // edge MLP (once)
    dim3 ge((O + 127) / 128, EROWS / 128);
    ec_gemm<<<ge, 256>>>(featPtr, lda, C, knn, w, O, ey);
    // BN stats + apply
    ec_stats_y<<<SBLK, O>>>(ey, O, EROWS / SBLK, psum, psq);
    bn_reduce<<<(O + 255) / 256, 256>>>(psum, psq, SBLK, O, 1.f / (float)EROWS, mean, rstd);
    ec_apply_y<<<BB * NN, O>>>(ey, O, mean, rstd, g, b, h, outOff);
}

extern "C" void kernel_launch(void* const* d_in, const int* in_sizes, int n_in,
                              void* d_out, int out_size)
{
    const float* x      = (const float*)d_in[0];
    const float* pos    = (const float*)d_in[1];
    const float* w1 = (const float*)d_in[2];  const float* g1 = (const float*)d_in[3];  const float* b1 = (const float*)d_in[4];
    const float* w2 = (const float*)d_in[5];  const float* g2 = (const float*)d_in[6];  const float* b2 = (const float*)d_in[7];
    const float* w3 = (const float*)d_in[8];  const float* g3 = (const float*)d_in[9];  const float* b3 = (const float*)d_in[10];
    const float* w4 = (const float*)d_in[11]; const float* g4 = (const float*)d_in[12]; const float* b4 = (const float*)d_in[13];
    const float* w5 = (const float*)d_in[14]; const float* g5 = (const float*)d_in[15]; const float* b5 = (const float*)d_in[16];
    const float* cls    = (const float*)d_in[17];
    const float* ln1g   = (const float*)d_in[18];
    const float* ln1b   = (const float*)d_in[19];
    const float* wqkv   = (const float*)d_in[20];
    const float* wout   = (const float*)d_in[21];
    const float* bout   = (const float*)d_in[22];
    const float* ln2g   = (const float*)d_in[23];
    const float* ln2b   = (const float*)d_in[24];
    const float* wff1   = (const float*)d_in[25];
    const float* bff1   = (const float*)d_in[26];
    const float* wff2   = (const float*)d_in[27];
    const float* bff2   = (const float*)d_in[28];
    float* out = (float*)d_out;

    float *h, *G, *sq, *ey, *psum, *psq, *mean, *rstd, *y5, *t, *ln, *qkv, *z, *ff;
    int* knn;
    cudaGetSymbolAddress((void**)&h, g_h);
    cudaGetSymbolAddress((void**)&G, g_G);
    cudaGetSymbolAddress((void**)&sq, g_sq);
    cudaGetSymbolAddress((void**)&knn, g_knn);
    cudaGetSymbolAddress((void**)&ey, g_ey);
    cudaGetSymbolAddress((void**)&psum, g_psum);
    cudaGetSymbolAddress((void**)&psq, g_psq);
    cudaGetSymbolAddress((void**)&mean, g_mean);
    cudaGetSymbolAddress((void**)&rstd, g_rstd);
    cudaGetSymbolAddress((void**)&y5, g_y5);
    cudaGetSymbolAddress((void**)&t, g_t);
    cudaGetSymbolAddress((void**)&ln, g_ln);
    cudaGetSymbolAddress((void**)&qkv, g_qkv);
    cudaGetSymbolAddress((void**)&z, g_z);
    cudaGetSymbolAddress((void**)&ff, g_ff);

    // ---- DGCNN backbone ----
    edge_layer(x,       3,   3,   w1, g1, b1, 64,  0,   h, G, sq, knn, ey, psum, psq, mean, rstd);
    edge_layer(h + 0,   512, 64,  w2, g2, b2, 64,  64,  h, G, sq, knn, ey, psum, psq, mean, rstd);
    edge_layer(h + 64,  512, 64,  w3, g3, b3, 128, 128, h, G, sq, knn, ey, psum, psq, mean, rstd);
    edge_layer(h + 128, 512, 128, w4, g4, b4, 256, 256, h, G, sq, knn, ey, psum, psq, mean, rstd);

    // ---- conv5: [16384,512] @ [1024,512]^T ----
    {
        dim3 gg(DD / 128, BB * NN / 128);
        sgemm<128, 128, 8, 8, 8, true, 0, false><<<gg, 256>>>(
            h, 512, 0, w5, 512, 0, nullptr, y5, DD, 0, BB * NN, DD, 512);
        bn5_partial<<<BB * NN / 256, 256>>>(y5, psum, psq);
        bn_reduce<<<(DD + 255) / 256, 256>>>(psum, psq, BB * NN / 256, DD,
                                             1.f / (8.f * 2048.f), mean, rstd);
        pool_kernel<<<TOK, 256>>>(y5, mean, rstd, g5, b5, cls, t);
    }

    // ---- transformer ----
    for (int i = 0; i < 6; i++) {
        const float* wqkv_i = wqkv + (size_t)i * DD * 3 * INNER;
        const float* wout_i = wout + (size_t)i * INNER * DD;
        const float* bout_i = bout + (size_t)i * DD;
        const float* wff1_i = wff1 + (size_t)i * DD * MLPD;
        const float* bff1_i = bff1 + (size_t)i * MLPD;
        const float* wff2_i = wff2 + (size_t)i * MLPD * DD;
        const float* bff2_i = bff2 + (size_t)i * DD;

        ln_kernel<<<TOK, 256>>>(t, pos, ln1g + i * DD, ln1b + i * DD, ln);

        dim3 gq((3 * INNER + 63) / 64, (TOK + 63) / 64);
        sgemm<64, 64, 8, 4, 4, false, 0, false><<<gq, 256>>>(
            ln, DD, 0, wqkv_i, 3 * INNER, 0, nullptr, qkv, 3 * INNER, 0, TOK, 3 * INNER, DD);

        attn_kernel<<<dim3(65, 8, BB), 128>>>(qkv, z);

        dim3 gp((DD + 63) / 64, (TOK + 63) / 64);
        sgemm<64, 64, 8, 4, 4, false, 0, true><<<gp, 256>>>(
            z, INNER, 0, wout_i, DD, 0, bout_i, t, DD, 0, TOK, DD, INNER);

        ln_kernel<<<TOK, 256>>>(t, nullptr, ln2g + i * DD, ln2b + i * DD, ln);

        dim3 gf1((MLPD + 63) / 64, (TOK + 63) / 64);
        sgemm<64, 64, 8, 4, 4, false, 1, false><<<gf1, 256>>>(
            ln, DD, 0, wff1_i, MLPD, 0, bff1_i, ff, MLPD, 0, TOK, MLPD, DD);

        dim3 gf2((DD + 63) / 64, (TOK + 63) / 64);
        sgemm<64, 64, 8, 4, 4, false, 0, true><<<gf2, 256>>>(
            ff, MLPD, 0, wff2_i, DD, 0, bff2_i, t, DD, 0, TOK, DD, MLPD);
    }

    out_copy<<<(BB * PP * DD + 255) / 256, 256>>>(t, out);
}

// round 7
// speedup vs baseline: 2.0935x; 1.3436x over previous
#include <cuda_runtime.h>
#include <cuda_bf16.h>
#include <cfloat>
#include <math.h>

// ---------------- problem constants ----------------
#define BB 8
#define NN 2048
#define KK 20
#define PP 64
#define PS 32
#define DD 1024
#define TOK (BB * (PP + 1))   // 520
#define INNER 512
#define MLPD 2048
#define EROWS (BB * NN * KK)  // 327680
#define SBLK 512

// ---------------- scratch ----------------
__device__ float g_h[BB * NN * 512];
__device__ float g_G[BB * NN * NN];
__device__ float g_sq[BB * NN];
__device__ int   g_knn[EROWS];
__device__ float g_ey[(size_t)EROWS * 256];
__device__ float g_psum[SBLK * 1024];
__device__ float g_psq[SBLK * 1024];
__device__ float g_mean[1024];
__device__ float g_rstd[1024];
__device__ float g_y5[BB * NN * DD];
__device__ float g_t[TOK * DD];
__device__ float g_ln[TOK * DD];
__device__ float g_qkv[TOK * 3 * INNER];
__device__ float g_z[TOK * INNER];
__device__ float g_ff[TOK * MLPD];

__device__ __forceinline__ float4 ld4(const float* p) { return *(const float4*)p; }

// ================= double-buffered 128x128x16 SGEMM =================
// C = act(A@B + bias)(+C). A:[M,K] lda. B: [K,N] ldb or [N,K] if TRANSB.
template <bool TRANSB, int ACT, bool ADDC>
__global__ __launch_bounds__(256, 2)
void gemm128(const float* __restrict__ A, int lda, size_t strideA,
             const float* __restrict__ Bm, int ldb, size_t strideB,
             const float* __restrict__ bias,
             float* __restrict__ C, int ldc, size_t strideC,
             int M, int N, int K)
{
    const int BK = 16;
    __shared__ float As[2][BK][128];
    __shared__ float Bs[2][BK][128];
    A  += (size_t)blockIdx.z * strideA;
    Bm += (size_t)blockIdx.z * strideB;
    C  += (size_t)blockIdx.z * strideC;
    int bm = blockIdx.y * 128, bn = blockIdx.x * 128;
    int tid = threadIdx.x;
    int trow = tid >> 4, tcol = tid & 15;

    float4 ra[2], rb[2];

    auto loadA = [&](int k0) {
#pragma unroll
        for (int i = 0; i < 2; i++) {
            int row = i * 64 + (tid >> 2), q = tid & 3;
            int gm = bm + row, gk = k0 + q * 4;
            if (k0 + BK <= K) {
                ra[i] = (gm < M) ? ld4(&A[(size_t)gm * lda + gk]) : make_float4(0, 0, 0, 0);
            } else {
                float v[4];
#pragma unroll
                for (int j = 0; j < 4; j++)
                    v[j] = (gm < M && gk + j < K) ? A[(size_t)gm * lda + gk + j] : 0.f;
                ra[i] = make_float4(v[0], v[1], v[2], v[3]);
            }
        }
    };
    auto loadB = [&](int k0) {
#pragma unroll
        for (int i = 0; i < 2; i++) {
            if (TRANSB) {
                int row = i * 64 + (tid >> 2), q = tid & 3;
                int gn = bn + row, gk = k0 + q * 4;
                if (k0 + BK <= K) {
                    rb[i] = (gn < N) ? ld4(&Bm[(size_t)gn * ldb + gk]) : make_float4(0, 0, 0, 0);
                } else {
                    float v[4];
#pragma unroll
                    for (int j = 0; j < 4; j++)
                        v[j] = (gn < N && gk + j < K) ? Bm[(size_t)gn * ldb + gk + j] : 0.f;
                    rb[i] = make_float4(v[0], v[1], v[2], v[3]);
                }
            } else {
                int krow = i * 8 + (tid >> 5), nq = tid & 31;
                int gk = k0 + krow, gn = bn + nq * 4;
                if (gk < K && gn < N) rb[i] = ld4(&Bm[(size_t)gk * ldb + gn]);
                else rb[i] = make_float4(0, 0, 0, 0);
            }
        }
    };
    auto storeA = [&](int p) {
#pragma unroll
        for (int i = 0; i < 2; i++) {
            int row = i * 64 + (tid >> 2), q = tid & 3;
            As[p][q * 4 + 0][row] = ra[i].x;
            As[p][q * 4 + 1][row] = ra[i].y;
            As[p][q * 4 + 2][row] = ra[i].z;
            As[p][q * 4 + 3][row] = ra[i].w;
        }
    };
    auto storeB = [&](int p) {
#pragma unroll
        for (int i = 0; i < 2; i++) {
            if (TRANSB) {
                int row = i * 64 + (tid >> 2), q = tid & 3;
                Bs[p][q * 4 + 0][row] = rb[i].x;
                Bs[p][q * 4 + 1][row] = rb[i].y;
                Bs[p][q * 4 + 2][row] = rb[i].z;
                Bs[p][q * 4 + 3][row] = rb[i].w;
            } else {
                int krow = i * 8 + (tid >> 5), nq = tid & 31;
                *(float4*)&Bs[p][krow][nq * 4] = rb[i];
            }
        }
    };

    float acc[8][8];
#pragma unroll
    for (int i = 0; i < 8; i++)
#pragma unroll
        for (int j = 0; j < 8; j++) acc[i][j] = 0.f;

    int nk = (K + BK - 1) / BK;
    loadA(0); loadB(0);
    storeA(0); storeB(0);
    __syncthreads();
    int p = 0;
    for (int it = 0; it < nk; it++) {
        if (it + 1 < nk) { loadA((it + 1) * BK); loadB((it + 1) * BK); }
#pragma unroll
        for (int k = 0; k < BK; k++) {
            float4 a0 = ld4(&As[p][k][trow * 8]);
            float4 a1 = ld4(&As[p][k][trow * 8 + 4]);
            float4 b0 = ld4(&Bs[p][k][tcol * 8]);
            float4 b1 = ld4(&Bs[p][k][tcol * 8 + 4]);
            float a[8] = {a0.x, a0.y, a0.z, a0.w, a1.x, a1.y, a1.z, a1.w};
            float b[8] = {b0.x, b0.y, b0.z, b0.w, b1.x, b1.y, b1.z, b1.w};
#pragma unroll
            for (int i = 0; i < 8; i++)
#pragma unroll
                for (int j = 0; j < 8; j++) acc[i][j] += a[i] * b[j];
        }
        if (it + 1 < nk) { storeA(p ^ 1); storeB(p ^ 1); }
        __syncthreads();
        p ^= 1;
    }
#pragma unroll
    for (int i = 0; i < 8; i++) {
        int gm = bm + trow * 8 + i;
        if (gm >= M) continue;
#pragma unroll
        for (int j = 0; j < 8; j++) {
            int gn = bn + tcol * 8 + j;
            if (gn >= N) continue;
            float v = acc[i][j];
            if (bias) v += bias[gn];
            if (ACT == 1) v = 0.5f * v * (1.f + erff(v * 0.70710678118654752f));
            size_t off = (size_t)gm * ldc + gn;
            if (ADDC) v += C[off];
            C[off] = v;
        }
    }
}

// ================= double-buffered 64x64x16 SGEMM (small-M) =================
template <bool TRANSB, int ACT, bool ADDC>
__global__ __launch_bounds__(256)
void gemm64(const float* __restrict__ A, int lda,
            const float* __restrict__ Bm, int ldb,
            const float* __restrict__ bias,
            float* __restrict__ C, int ldc,
            int M, int N, int K)
{
    const int BK = 16;
    __shared__ float As[2][BK][64];
    __shared__ float Bs[2][BK][64];
    int bm = blockIdx.y * 64, bn = blockIdx.x * 64;
    int tid = threadIdx.x;
    int trow = tid >> 4, tcol = tid & 15;
    float4 ra, rb;

    auto loadA = [&](int k0) {
        int row = tid >> 2, q = tid & 3;
        int gm = bm + row, gk = k0 + q * 4;
        if (k0 + BK <= K) {
            ra = (gm < M) ? ld4(&A[(size_t)gm * lda + gk]) : make_float4(0, 0, 0, 0);
        } else {
            float v[4];
#pragma unroll
            for (int j = 0; j < 4; j++)
                v[j] = (gm < M && gk + j < K) ? A[(size_t)gm * lda + gk + j] : 0.f;
            ra = make_float4(v[0], v[1], v[2], v[3]);
        }
    };
    auto loadB = [&](int k0) {
        if (TRANSB) {
            int row = tid >> 2, q = tid & 3;
            int gn = bn + row, gk = k0 + q * 4;
            if (k0 + BK <= K) {
                rb = (gn < N) ? ld4(&Bm[(size_t)gn * ldb + gk]) : make_float4(0, 0, 0, 0);
            } else {
                float v[4];
#pragma unroll
                for (int j = 0; j < 4; j++)
                    v[j] = (gn < N && gk + j < K) ? Bm[(size_t)gn * ldb + gk + j] : 0.f;
                rb = make_float4(v[0], v[1], v[2], v[3]);
            }
        } else {
            int krow = tid >> 4, nq = tid & 15;
            int gk = k0 + krow, gn = bn + nq * 4;
            rb = (gk < K && gn < N) ? ld4(&Bm[(size_t)gk * ldb + gn]) : make_float4(0, 0, 0, 0);
        }
    };
    auto storeA = [&](int p) {
        int row = tid >> 2, q = tid & 3;
        As[p][q * 4 + 0][row] = ra.x;
        As[p][q * 4 + 1][row] = ra.y;
        As[p][q * 4 + 2][row] = ra.z;
        As[p][q * 4 + 3][row] = ra.w;
    };
    auto storeB = [&](int p) {
        if (TRANSB) {
            int row = tid >> 2, q = tid & 3;
            Bs[p][q * 4 + 0][row] = rb.x;
            Bs[p][q * 4 + 1][row] = rb.y;
            Bs[p][q * 4 + 2][row] = rb.z;
            Bs[p][q * 4 + 3][row] = rb.w;
        } else {
            int krow = tid >> 4, nq = tid & 15;
            *(float4*)&Bs[p][krow][nq * 4] = rb;
        }
    };

    float acc[4][4];
#pragma unroll
    for (int i = 0; i < 4; i++)
#pragma unroll
        for (int j = 0; j < 4; j++) acc[i][j] = 0.f;

    int nk = (K + BK - 1) / BK;
    loadA(0); loadB(0);
    storeA(0); storeB(0);
    __syncthreads();
    int p = 0;
    for (int it = 0; it < nk; it++) {
        if (it + 1 < nk) { loadA((it + 1) * BK); loadB((it + 1) * BK); }
#pragma unroll
        for (int k = 0; k < BK; k++) {
            float4 a4 = ld4(&As[p][k][trow * 4]);
            float4 b4 = ld4(&Bs[p][k][tcol * 4]);
            float a[4] = {a4.x, a4.y, a4.z, a4.w};
            float b[4] = {b4.x, b4.y, b4.z, b4.w};
#pragma unroll
            for (int i = 0; i < 4; i++)
#pragma unroll
                for (int j = 0; j < 4; j++) acc[i][j] += a[i] * b[j];
        }
        if (it + 1 < nk) { storeA(p ^ 1); storeB(p ^ 1); }
        __syncthreads();
        p ^= 1;
    }
#pragma unroll
    for (int i = 0; i < 4; i++) {
        int gm = bm + trow * 4 + i;
        if (gm >= M) continue;
#pragma unroll
        for (int j = 0; j < 4; j++) {
            int gn = bn + tcol * 4 + j;
            if (gn >= N) continue;
            float v = acc[i][j];
            if (bias) v += bias[gn];
            if (ACT == 1) v = 0.5f * v * (1.f + erff(v * 0.70710678118654752f));
            size_t off = (size_t)gm * ldc + gn;
            if (ADDC) v += C[off];
            C[off] = v;
        }
    }
}

// ================= gather-fused EdgeConv GEMM (double-buffered) =================
// y[r][o] = f(r,:) . w[o,:];  f(r,c)= c<C ? feat[nbr]-feat[ctr] : feat[ctr]
template <int BN>
__global__ __launch_bounds__(256, 2)
void ec_gemm(const float* __restrict__ feat, int stride, int C,
             const int* __restrict__ knn,
             const float* __restrict__ w, int O,
             float* __restrict__ y)
{
    const int BK = 16;
    constexpr int TN = BN / 16;
    __shared__ float As[2][BK][128];
    __shared__ float Bs[2][BK][BN];
    __shared__ int s_nbr[128], s_ctr[128];
    int tid = threadIdx.x;
    int bm = blockIdx.y * 128, bn0 = blockIdx.x * BN;
    int C2 = 2 * C;
    for (int i = tid; i < 128; i += 256) {
        int r = bm + i;
        int pnt = r / KK;
        int b = pnt >> 11;
        int j = knn[r];
        s_nbr[i] = ((b << 11) + j) * stride;
        s_ctr[i] = pnt * stride;
    }
    __syncthreads();
    int trow = tid >> 4, tcol = tid & 15;
    bool c4ok = ((C & 3) == 0);

    float4 ra[2], rb[BN / 64];

    auto loadA = [&](int k0) {
#pragma unroll
        for (int i = 0; i < 2; i++) {
            int row = i * 64 + (tid >> 2), q = tid & 3;
            int c4 = k0 + q * 4;
            if (k0 + BK <= C2 && c4ok) {
                if (c4 + 4 <= C) {
                    float4 nb = ld4(&feat[s_nbr[row] + c4]);
                    float4 ct = ld4(&feat[s_ctr[row] + c4]);
                    ra[i] = make_float4(nb.x - ct.x, nb.y - ct.y, nb.z - ct.z, nb.w - ct.w);
                } else {
                    ra[i] = ld4(&feat[s_ctr[row] + c4 - C]);
                }
            } else {
                float v[4];
#pragma unroll
                for (int j = 0; j < 4; j++) {
                    int c = c4 + j;
                    float x = 0.f;
                    if (c < C2) {
                        if (c < C) x = feat[s_nbr[row] + c] - feat[s_ctr[row] + c];
                        else       x = feat[s_ctr[row] + c - C];
                    }
                    v[j] = x;
                }
                ra[i] = make_float4(v[0], v[1], v[2], v[3]);
            }
        }
    };
    auto loadB = [&](int k0) {
#pragma unroll
        for (int i = 0; i < BN / 64; i++) {
            int row = i * 64 + (tid >> 2), q = tid & 3;
            int gn = bn0 + row, gk = k0 + q * 4;
            if (k0 + BK <= C2 && c4ok) {
                rb[i] = (gn < O) ? ld4(&w[(size_t)gn * C2 + gk]) : make_float4(0, 0, 0, 0);
            } else {
                float v[4];
#pragma unroll
                for (int j = 0; j < 4; j++)
                    v[j] = (gn < O && gk + j < C2) ? w[(size_t)gn * C2 + gk + j] : 0.f;
                rb[i] = make_float4(v[0], v[1], v[2], v[3]);
            }
        }
    };
    auto storeA = [&](int p) {
#pragma unroll
        for (int i = 0; i < 2; i++) {
            int row = i * 64 + (tid >> 2), q = tid & 3;
            As[p][q * 4 + 0][row] = ra[i].x;
            As[p][q * 4 + 1][row] = ra[i].y;
            As[p][q * 4 + 2][row] = ra[i].z;
            As[p][q * 4 + 3][row] = ra[i].w;
        }
    };
    auto storeB = [&](int p) {
#pragma unroll
        for (int i = 0; i < BN / 64; i++) {
            int row = i * 64 + (tid >> 2), q = tid & 3;
            Bs[p][q * 4 + 0][row] = rb[i].x;
            Bs[p][q * 4 + 1][row] = rb[i].y;
            Bs[p][q * 4 + 2][row] = rb[i].z;
            Bs[p][q * 4 + 3][row] = rb[i].w;
        }
    };

    float acc[8][TN];
#pragma unroll
    for (int i = 0; i < 8; i++)
#pragma unroll
        for (int j = 0; j < TN; j++) acc[i][j] = 0.f;

    int nk = (C2 + BK - 1) / BK;
    loadA(0); loadB(0);
    storeA(0); storeB(0);
    __syncthreads();
    int p = 0;
    for (int it = 0; it < nk; it++) {
        if (it + 1 < nk) { loadA((it + 1) * BK); loadB((it + 1) * BK); }
#pragma unroll
        for (int k = 0; k < BK; k++) {
            float a[8], b[TN];
            float4 a0 = ld4(&As[p][k][trow * 8]);
            float4 a1 = ld4(&As[p][k][trow * 8 + 4]);
            a[0] = a0.x; a[1] = a0.y; a[2] = a0.z; a[3] = a0.w;
            a[4] = a1.x; a[5] = a1.y; a[6] = a1.z; a[7] = a1.w;
#pragma unroll
            for (int j = 0; j < TN / 4; j++) {
                float4 b4 = ld4(&Bs[p][k][tcol * TN + j * 4]);
                b[j * 4 + 0] = b4.x; b[j * 4 + 1] = b4.y;
                b[j * 4 + 2] = b4.z; b[j * 4 + 3] = b4.w;
            }
#pragma unroll
            for (int i = 0; i < 8; i++)
#pragma unroll
                for (int j = 0; j < TN; j++) acc[i][j] += a[i] * b[j];
        }
        if (it + 1 < nk) { storeA(p ^ 1); storeB(p ^ 1); }
        __syncthreads();
        p ^= 1;
    }
#pragma unroll
    for (int i = 0; i < 8; i++) {
        int m = bm + trow * 8 + i;
#pragma unroll
        for (int j = 0; j < TN; j++) {
            int col = bn0 + tcol * TN + j;
            y[(size_t)m * O + col] = acc[i][j];
        }
    }
}

// ---------------- deterministic BN stats over y rows ----------------
__global__ void ec_stats_y(const float* __restrict__ y, int O, int rowsPer,
                           float* __restrict__ psum, float* __restrict__ psq)
{
    int blk = blockIdx.x;
    int o = threadIdx.x;
    float s = 0.f, s2 = 0.f;
    int r0 = blk * rowsPer;
    for (int r = r0; r < r0 + rowsPer; r++) {
        float v = y[(size_t)r * O + o];
        s += v; s2 += v * v;
    }
    psum[(size_t)blk * O + o] = s;
    psq[(size_t)blk * O + o] = s2;
}

__global__ void bn_reduce(const float* __restrict__ psum, const float* __restrict__ psq,
                          int npart, int O, float cnt_inv,
                          float* __restrict__ mean, float* __restrict__ rstd)
{
    int o = blockIdx.x * blockDim.x + threadIdx.x;
    if (o >= O) return;
    float s = 0.f, s2 = 0.f;
    for (int i = 0; i < npart; i++) {
        s  += psum[(size_t)i * O + o];
        s2 += psq[(size_t)i * O + o];
    }
    float mu = s * cnt_inv;
    float var = s2 * cnt_inv - mu * mu;
    mean[o] = mu;
    rstd[o] = rsqrtf(var + 1e-5f);
}

// ---------------- BN + lrelu + max over k ----------------
__global__ void ec_apply_y(const float* __restrict__ y, int O,
                           const float* __restrict__ mean, const float* __restrict__ rstd,
                           const float* __restrict__ gam, const float* __restrict__ bet,
                           float* __restrict__ outH, int outOff)
{
    int bn = blockIdx.x;
    int o = threadIdx.x;
    float mu = mean[o], rs = rstd[o], gg = gam[o], bb = bet[o];
    float m = -FLT_MAX;
    for (int kk = 0; kk < KK; kk++) {
        float v = y[((size_t)bn * KK + kk) * O + o];
        v = (v - mu) * rs * gg + bb;
        v = (v >= 0.f) ? v : 0.2f * v;
        m = fmaxf(m, v);
    }
    outH[(size_t)bn * 512 + outOff + o] = m;
}

__global__ void diag_kernel(const float* __restrict__ G, float* __restrict__ sq)
{
    int bn = blockIdx.x * blockDim.x + threadIdx.x;
    if (bn < BB * NN) {
        int b = bn >> 11, n = bn & 2047;
        sq[bn] = G[((size_t)b * NN + n) * NN + n];
    }
}

// ---------------- kNN top-20 ----------------
__global__ void knn_select(const float* __restrict__ G, const float* __restrict__ sq,
                           int* __restrict__ out)
{
    int bn = blockIdx.x;
    int b = bn >> 11, n = bn & 2047;
    __shared__ float dist[NN];
    __shared__ float wv[8];
    __shared__ int wi[8];
    int tid = threadIdx.x;   // 256
    int lane = tid & 31, warp = tid >> 5;
    const float* row = G + ((size_t)b * NN + n) * NN;
    const float* sqb = sq + (b << 11);
    float sqn = sqb[n];
    for (int j = tid; j < NN; j += 256)
        dist[j] = 2.f * row[j] - sqn - sqb[j];
    __syncthreads();
    for (int sel = 0; sel < KK; sel++) {
        float bv = -FLT_MAX; int bi = 0x7fffffff;
#pragma unroll
        for (int u = 0; u < NN / 256; u++) {
            int j = u * 256 + tid;
            float v = dist[j];
            if (v > bv) { bv = v; bi = j; }
        }
#pragma unroll
        for (int off = 16; off > 0; off >>= 1) {
            float ov = __shfl_down_sync(0xffffffffu, bv, off);
            int oi = __shfl_down_sync(0xffffffffu, bi, off);
            if (ov > bv || (ov == bv && oi < bi)) { bv = ov; bi = oi; }
        }
        if (lane == 0) { wv[warp] = bv; wi[warp] = bi; }
        __syncthreads();
        if (tid == 0) {
            float fv = wv[0]; int fi = wi[0];
#pragma unroll
            for (int w = 1; w < 8; w++) {
                if (wv[w] > fv || (wv[w] == fv && wi[w] < fi)) { fv = wv[w]; fi = wi[w]; }
            }
            out[bn * KK + sel] = fi;
            dist[fi] = -FLT_MAX;
        }
        __syncthreads();
    }
}

// ---------------- conv5 BN partials ----------------
__global__ void bn5_partial(const float* __restrict__ y5, float* __restrict__ psum,
                            float* __restrict__ psq)
{
    int blk = blockIdx.x;
    int t0 = blk * 256;
    int tid = threadIdx.x;
    float s[4] = {0, 0, 0, 0}, s2[4] = {0, 0, 0, 0};
    for (int t = t0; t < t0 + 256; t++) {
        const float* row = y5 + (size_t)t * DD;
#pragma unroll
        for (int i = 0; i < 4; i++) {
            float v = row[tid + i * 256];
            s[i] += v; s2[i] += v * v;
        }
    }
#pragma unroll
    for (int i = 0; i < 4; i++) {
        psum[(size_t)blk * DD + tid + i * 256] = s[i];
        psq[(size_t)blk * DD + tid + i * 256] = s2[i];
    }
}

// ---------------- BN5 + leaky + patch max-pool + cls ----------------
__global__ void pool_kernel(const float* __restrict__ y5, const float* __restrict__ mean,
                            const float* __restrict__ rstd, const float* __restrict__ g5,
                            const float* __restrict__ b5, const float* __restrict__ cls,
                            float* __restrict__ t)
{
    int tok = blockIdx.x;
    int b = tok / 65, l = tok - b * 65;
    int tid = threadIdx.x;
    if (l == 0) {
        for (int d = tid; d < DD; d += 256) t[(size_t)tok * DD + d] = cls[d];
    } else {
        int p = l - 1;
        int base = b * NN + p * PS;
        for (int d = tid; d < DD; d += 256) {
            float mu = mean[d], rs = rstd[d], gg = g5[d], bb = b5[d];
            float m = -FLT_MAX;
            for (int s = 0; s < PS; s++) {
                float v = y5[(size_t)(base + s) * DD + d];
                v = (v - mu) * rs * gg + bb;
                v = (v >= 0.f) ? v : 0.2f * v;
                m = fmaxf(m, v);
            }
            t[(size_t)tok * DD + d] = m;
        }
    }
}

// ---------------- LayerNorm (optional fused pos-add) ----------------
__global__ void ln_kernel(float* __restrict__ t, const float* __restrict__ pos,
                          const float* __restrict__ g, const float* __restrict__ b,
                          float* __restrict__ out)
{
    int tok = blockIdx.x, tid = threadIdx.x;
    __shared__ float rs1[256], rs2[256];
    float* trow = t + (size_t)tok * DD;
    float loc[4];
    float s = 0.f, s2 = 0.f;
#pragma unroll
    for (int i = 0; i < 4; i++) {
        int d = tid + i * 256;
        float v = trow[d];
        if (pos) { v += pos[(size_t)tok * DD + d]; trow[d] = v; }
        loc[i] = v; s += v; s2 += v * v;
    }
    rs1[tid] = s; rs2[tid] = s2;
    __syncthreads();
    for (int st = 128; st > 0; st >>= 1) {
        if (tid < st) { rs1[tid] += rs1[tid + st]; rs2[tid] += rs2[tid + st]; }
        __syncthreads();
    }
    float mean = rs1[0] * (1.f / DD);
    float var = rs2[0] * (1.f / DD) - mean * mean;
    float rstd = rsqrtf(var + 1e-5f);
#pragma unroll
    for (int i = 0; i < 4; i++) {
        int d = tid + i * 256;
        out[(size_t)tok * DD + d] = (loc[i] - mean) * rstd * g[d] + b[d];
    }
}

// ---------------- attention ----------------
__global__ void attn_kernel(const float* __restrict__ qkv, float* __restrict__ z)
{
    int l = blockIdx.x, hh = blockIdx.y, b = blockIdx.z;
    int tid = threadIdx.x;   // 128
    __shared__ float sq_[64];
    __shared__ float sc[65];
    __shared__ float sinv;
    const float* qrow = qkv + (size_t)(b * 65 + l) * 1536 + hh * 64;
    if (tid < 64) sq_[tid] = qrow[tid];
    __syncthreads();
    if (tid < 65) {
        const float* krow = qkv + (size_t)(b * 65 + tid) * 1536 + 512 + hh * 64;
        float s = 0.f;
#pragma unroll 16
        for (int d = 0; d < 64; d++) s += sq_[d] * krow[d];
        sc[tid] = s * 0.125f;
    }
    __syncthreads();
    if (tid == 0) {
        float mx = -FLT_MAX;
        for (int m = 0; m < 65; m++) mx = fmaxf(mx, sc[m]);
        float sum = 0.f;
        for (int m = 0; m < 65; m++) { float e = expf(sc[m] - mx); sc[m] = e; sum += e; }
        sinv = 1.f / sum;
    }
    __syncthreads();
    if (tid < 64) {
        float inv = sinv;
        float acc = 0.f;
        for (int m = 0; m < 65; m++) {
            const float* vrow = qkv + (size_t)(b * 65 + m) * 1536 + 1024 + hh * 64;
            acc += sc[m] * vrow[tid];
        }
        z[(size_t)(b * 65 + l) * INNER + hh * 64 + tid] = acc * inv;
    }
}

__global__ void out_copy(const float* __restrict__ t, float* __restrict__ out)
{
    int i = blockIdx.x * blockDim.x + threadIdx.x;
    if (i < BB * PP * DD) {
        int d = i & (DD - 1);
        int bp = i >> 10;
        int b = bp >> 6, p = bp & 63;
        out[i] = t[((size_t)(b * 65 + 1 + p) << 10) + d];
    }
}

// ---------------- host driver ----------------
static void edge_layer(const float* featPtr, int lda, int C,
                       const float* w, const float* g, const float* b,
                       int O, int outOff,
                       float* h, float* G, float* sq, int* knn, float* ey,
                       float* psum, float* psq, float* mean, float* rstd)
{
    dim3 gg(NN / 128, NN / 128, BB);
    gemm128<true, 0, false><<<gg, 256>>>(
        featPtr, lda, (size_t)NN * lda, featPtr, lda, (size_t)NN * lda,
        nullptr, G, NN, (size_t)NN * NN, NN, NN, C);
    diag_kernel<<<(BB * NN + 255) / 256, 256>>>(G, sq);
    knn_select<<<BB * NN, 256>>>(G, sq, knn);
    if (O == 64) {
        dim3 ge(1, EROWS / 128);
        ec_gemm<64><<<ge, 256>>>(featPtr, lda, C, knn, w, O, ey);
    } else {
        dim3 ge(O / 128, EROWS / 128);
        ec_gemm<128><<<ge, 256>>>(featPtr, lda, C, knn, w, O, ey);
    }
    ec_stats_y<<<SBLK, O>>>(ey, O, EROWS / SBLK, psum, psq);
    bn_reduce<<<(O + 255) / 256, 256>>>(psum, psq, SBLK, O, 1.f / (float)EROWS, mean, rstd);
    ec_apply_y<<<BB * NN, O>>>(ey, O, mean, rstd, g, b, h, outOff);
}

extern "C" void kernel_launch(void* const* d_in, const int* in_sizes, int n_in,
                              void* d_out, int out_size)
{
    const float* x      = (const float*)d_in[0];
    const float* pos    = (const float*)d_in[1];
    const float* w1 = (const float*)d_in[2];  const float* g1 = (const float*)d_in[3];  const float* b1 = (const float*)d_in[4];
    const float* w2 = (const float*)d_in[5];  const float* g2 = (const float*)d_in[6];  const float* b2 = (const float*)d_in[7];
    const float* w3 = (const float*)d_in[8];  const float* g3 = (const float*)d_in[9];  const float* b3 = (const float*)d_in[10];
    const float* w4 = (const float*)d_in[11]; const float* g4 = (const float*)d_in[12]; const float* b4 = (const float*)d_in[13];
    const float* w5 = (const float*)d_in[14]; const float* g5 = (const float*)d_in[15]; const float* b5 = (const float*)d_in[16];
    const float* cls    = (const float*)d_in[17];
    const float* ln1g   = (const float*)d_in[18];
    const float* ln1b   = (const float*)d_in[19];
    const float* wqkv   = (const float*)d_in[20];
    const float* wout   = (const float*)d_in[21];
    const float* bout   = (const float*)d_in[22];
    const float* ln2g   = (const float*)d_in[23];
    const float* ln2b   = (const float*)d_in[24];
    const float* wff1   = (const float*)d_in[25];
    const float* bff1   = (const float*)d_in[26];
    const float* wff2   = (const float*)d_in[27];
    const float* bff2   = (const float*)d_in[28];
    float* out = (float*)d_out;

    float *h, *G, *sq, *ey, *psum, *psq, *mean, *rstd, *y5, *t, *ln, *qkv, *z, *ff;
    int* knn;
    cudaGetSymbolAddress((void**)&h, g_h);
    cudaGetSymbolAddress((void**)&G, g_G);
    cudaGetSymbolAddress((void**)&sq, g_sq);
    cudaGetSymbolAddress((void**)&knn, g_knn);
    cudaGetSymbolAddress((void**)&ey, g_ey);
    cudaGetSymbolAddress((void**)&psum, g_psum);
    cudaGetSymbolAddress((void**)&psq, g_psq);
    cudaGetSymbolAddress((void**)&mean, g_mean);
    cudaGetSymbolAddress((void**)&rstd, g_rstd);
    cudaGetSymbolAddress((void**)&y5, g_y5);
    cudaGetSymbolAddress((void**)&t, g_t);
    cudaGetSymbolAddress((void**)&ln, g_ln);
    cudaGetSymbolAddress((void**)&qkv, g_qkv);
    cudaGetSymbolAddress((void**)&z, g_z);
    cudaGetSymbolAddress((void**)&ff, g_ff);

    // ---- DGCNN backbone ----
    edge_layer(x,       3,   3,   w1, g1, b1, 64,  0,   h, G, sq, knn, ey, psum, psq, mean, rstd);
    edge_layer(h + 0,   512, 64,  w2, g2, b2, 64,  64,  h, G, sq, knn, ey, psum, psq, mean, rstd);
    edge_layer(h + 64,  512, 64,  w3, g3, b3, 128, 128, h, G, sq, knn, ey, psum, psq, mean, rstd);
    edge_layer(h + 128, 512, 128, w4, g4, b4, 256, 256, h, G, sq, knn, ey, psum, psq, mean, rstd);

    // ---- conv5 ----
    {
        dim3 gg(DD / 128, BB * NN / 128);
        gemm128<true, 0, false><<<gg, 256>>>(
            h, 512, 0, w5, 512, 0, nullptr, y5, DD, 0, BB * NN, DD, 512);
        bn5_partial<<<BB * NN / 256, 256>>>(y5, psum, psq);
        bn_reduce<<<(DD + 255) / 256, 256>>>(psum, psq, BB * NN / 256, DD,
                                             1.f / (8.f * 2048.f), mean, rstd);
        pool_kernel<<<TOK, 256>>>(y5, mean, rstd, g5, b5, cls, t);
    }

    // ---- transformer ----
    for (int i = 0; i < 6; i++) {
        const float* wqkv_i = wqkv + (size_t)i * DD * 3 * INNER;
        const float* wout_i = wout + (size_t)i * INNER * DD;
        const float* bout_i = bout + (size_t)i * DD;
        const float* wff1_i = wff1 + (size_t)i * DD * MLPD;
        const float* bff1_i = bff1 + (size_t)i * MLPD;
        const float* wff2_i = wff2 + (size_t)i * MLPD * DD;
        const float* bff2_i = bff2 + (size_t)i * DD;

        ln_kernel<<<TOK, 256>>>(t, pos, ln1g + i * DD, ln1b + i * DD, ln);

        dim3 gq(3 * INNER / 64, (TOK + 63) / 64);
        gemm64<false, 0, false><<<gq, 256>>>(ln, DD, wqkv_i, 3 * INNER, nullptr,
                                             qkv, 3 * INNER, TOK, 3 * INNER, DD);

        attn_kernel<<<dim3(65, 8, BB), 128>>>(qkv, z);

        dim3 gp(DD / 64, (TOK + 63) / 64);
        gemm64<false, 0, true><<<gp, 256>>>(z, INNER, wout_i, DD, bout_i,
                                            t, DD, TOK, DD, INNER);

        ln_kernel<<<TOK, 256>>>(t, nullptr, ln2g + i * DD, ln2b + i * DD, ln);

        dim3 gf1(MLPD / 64, (TOK + 63) / 64);
        gemm64<false, 1, false><<<gf1, 256>>>(ln, DD, wff1_i, MLPD, bff1_i,
                                              ff, MLPD, TOK, MLPD, DD);

        dim3 gf2(DD / 64, (TOK + 63) / 64);
        gemm64<false, 0, true><<<gf2, 256>>>(ff, MLPD, wff2_i, DD, bff2_i,
                                             t, DD, TOK, DD, MLPD);
    }

    out_copy<<<(BB * PP * DD + 255) / 256, 256>>>(t, out);
}